// round 15
// baseline (speedup 1.0000x reference)
#include <cuda_runtime.h>
#include <cuda_bf16.h>
#include <math.h>
#include <stdint.h>

#define BB 2
#define SS 4096
#define DMD 768
#define NH 12
#define HDD 64
#define MROWS (BB*SS)

// Scratch (static device globals — allocation-free rule)
__device__ __align__(16) __nv_bfloat16 g_q[MROWS*DMD];
__device__ __align__(16) __nv_bfloat16 g_k[MROWS*DMD];
__device__ __align__(16) __nv_bfloat16 g_v[MROWS*DMD];
__device__ __align__(16) __nv_bfloat16 g_attn[MROWS*DMD];
__device__ __align__(16) __nv_bfloat16 g_x[MROWS*DMD];
__device__ __align__(16) __nv_bfloat16 g_wq[DMD*DMD];
__device__ __align__(16) __nv_bfloat16 g_wk[DMD*DMD];
__device__ __align__(16) __nv_bfloat16 g_wv[DMD*DMD];
__device__ __align__(16) __nv_bfloat16 g_wo[DMD*DMD];
__device__ __align__(16) float         g_tmp[MROWS*DMD];

// ---------------------------------------------------------------------------
// Helpers
// ---------------------------------------------------------------------------
__device__ __forceinline__ uint32_t packbf(float a, float b) {
    __nv_bfloat162 h = __floats2bfloat162_rn(a, b);
    return *(uint32_t*)&h;
}
__device__ __forceinline__ float bflo(uint32_t w) {
    return __bfloat162float(*(__nv_bfloat16*)&w);
}
__device__ __forceinline__ float bfhi(uint32_t w) {
    uint16_t h = (uint16_t)(w >> 16);
    return __bfloat162float(*(__nv_bfloat16*)&h);
}
__device__ __forceinline__ float ex2f(float x) {
    float y;
    asm("ex2.approx.f32 %0, %1;" : "=f"(y) : "f"(x));
    return y;
}
__device__ __forceinline__ void mma_bf16(float* c, const uint32_t* a,
                                         uint32_t b0, uint32_t b1) {
    asm volatile(
        "mma.sync.aligned.m16n8k16.row.col.f32.bf16.bf16.f32 "
        "{%0,%1,%2,%3}, {%4,%5,%6,%7}, {%8,%9}, {%0,%1,%2,%3};"
        : "+f"(c[0]), "+f"(c[1]), "+f"(c[2]), "+f"(c[3])
        : "r"(a[0]), "r"(a[1]), "r"(a[2]), "r"(a[3]), "r"(b0), "r"(b1));
}
__device__ __forceinline__ void cp16(uint32_t s, const void* g) {
    asm volatile("cp.async.cg.shared.global [%0], [%1], 16;" :: "r"(s), "l"(g));
}
__device__ __forceinline__ void cp_commit() {
    asm volatile("cp.async.commit_group;");
}
template<int N> __device__ __forceinline__ void cp_wait() {
    asm volatile("cp.async.wait_group %0;" :: "n"(N));
}
__device__ __forceinline__ void ldsm4(uint32_t& r0, uint32_t& r1,
                                      uint32_t& r2, uint32_t& r3, uint32_t a) {
    asm volatile("ldmatrix.sync.aligned.m8n8.x4.shared.b16 "
                 "{%0,%1,%2,%3}, [%4];"
                 : "=r"(r0), "=r"(r1), "=r"(r2), "=r"(r3) : "r"(a));
}
__device__ __forceinline__ void ldsm4t(uint32_t& r0, uint32_t& r1,
                                       uint32_t& r2, uint32_t& r3, uint32_t a) {
    asm volatile("ldmatrix.sync.aligned.m8n8.x4.trans.shared.b16 "
                 "{%0,%1,%2,%3}, [%4];"
                 : "=r"(r0), "=r"(r1), "=r"(r2), "=r"(r3) : "r"(a));
}
__device__ __forceinline__ uint32_t smaddr(const void* p) {
    return (uint32_t)__cvta_generic_to_shared(p);
}

// ---------------------------------------------------------------------------
// fp32 -> bf16 conversion (vectorized); single-tensor and fused 4-weight forms
// ---------------------------------------------------------------------------
__global__ __launch_bounds__(256) void f2bf(
    const float* __restrict__ in, __nv_bfloat16* __restrict__ out, int n)
{
    int i = (blockIdx.x * blockDim.x + threadIdx.x) * 4;
    if (i >= n) return;
    float4 v = *(const float4*)(in + i);
    uint2 o;
    o.x = packbf(v.x, v.y);
    o.y = packbf(v.z, v.w);
    *(uint2*)(out + i) = o;
}

__global__ __launch_bounds__(256) void f2bf_w4(
    const float* __restrict__ w0, const float* __restrict__ w1,
    const float* __restrict__ w2, const float* __restrict__ w3,
    __nv_bfloat16* __restrict__ o0, __nv_bfloat16* __restrict__ o1,
    __nv_bfloat16* __restrict__ o2, __nv_bfloat16* __restrict__ o3)
{
    int z = blockIdx.y;
    const float* in = (z == 0) ? w0 : (z == 1) ? w1 : (z == 2) ? w2 : w3;
    __nv_bfloat16* out = (z == 0) ? o0 : (z == 1) ? o1 : (z == 2) ? o2 : o3;
    int i = (blockIdx.x * blockDim.x + threadIdx.x) * 4;
    if (i >= DMD * DMD) return;
    float4 v = *(const float4*)(in + i);
    uint2 o;
    o.x = packbf(v.x, v.y);
    o.y = packbf(v.z, v.w);
    *(uint2*)(out + i) = o;
}

// ---------------------------------------------------------------------------
// bf16 GEMM core: out[M,N] = X[M,K] @ W[N,K]^T (+bias) (+residual)
// Tile 128x64, BK=32, 8 warps (4m x 2n), cp.async double-buffered.
// Optional fused RoPE epilogue (for Q/K projections).
// ---------------------------------------------------------------------------
#define GSW 20
#define RT_STRIDE 34   // rope tile row stride in words (68 bf16)

template<bool OUT_BF16, bool HAS_RES>
__device__ __forceinline__ void gemm_body(
    const __nv_bfloat16* __restrict__ X, const __nv_bfloat16* __restrict__ W,
    const float* __restrict__ bias, const float* __restrict__ residual,
    void* __restrict__ outv,
    uint32_t (*As)[128*GSW], uint32_t (*Bs)[64*GSW],
    const float* __restrict__ cosb, const float* __restrict__ sinb,
    float qscale, bool do_rope)
{
    const int tid  = threadIdx.x;
    const int warp = tid >> 5;
    const int lane = tid & 31;
    const int g    = lane >> 2;
    const int t    = lane & 3;
    const int wm   = warp & 3;
    const int wn   = warp >> 2;
    const int row0 = blockIdx.y * 128;
    const int col0 = blockIdx.x * 64;

    uint32_t asa[2] = { smaddr(As[0]), smaddr(As[1]) };
    uint32_t bsa[2] = { smaddr(Bs[0]), smaddr(Bs[1]) };

    const int ar = tid >> 2;
    const int ac8 = (tid & 3) * 8;

    {
        cp16(asa[0] + (ar * GSW + ac8/2) * 4, X + (size_t)(row0 + ar) * DMD + ac8);
        cp16(asa[0] + ((ar + 64) * GSW + ac8/2) * 4,
             X + (size_t)(row0 + ar + 64) * DMD + ac8);
        cp16(bsa[0] + (ar * GSW + ac8/2) * 4, W + (size_t)(col0 + ar) * DMD + ac8);
        cp_commit();
    }

    float c[2][4][4] = {};
    int buf = 0;

    const int NKI = DMD / 32;
    for (int ki = 0; ki < NKI; ki++) {
        if (ki + 1 < NKI) {
            const int k0 = (ki + 1) * 32;
            const int nb = buf ^ 1;
            cp16(asa[nb] + (ar * GSW + ac8/2) * 4,
                 X + (size_t)(row0 + ar) * DMD + k0 + ac8);
            cp16(asa[nb] + ((ar + 64) * GSW + ac8/2) * 4,
                 X + (size_t)(row0 + ar + 64) * DMD + k0 + ac8);
            cp16(bsa[nb] + (ar * GSW + ac8/2) * 4,
                 W + (size_t)(col0 + ar) * DMD + k0 + ac8);
            cp_commit();
            cp_wait<1>();
        } else {
            cp_wait<0>();
        }
        __syncthreads();

        const uint32_t* Ap = As[buf];
        const uint32_t* Bp = Bs[buf];
        #pragma unroll
        for (int kt = 0; kt < 2; kt++) {
            uint32_t a[2][4];
            #pragma unroll
            for (int mt = 0; mt < 2; mt++) {
                int rm = wm * 32 + mt * 16;
                a[mt][0] = Ap[(rm + g    ) * GSW + kt * 8 + t    ];
                a[mt][1] = Ap[(rm + g + 8) * GSW + kt * 8 + t    ];
                a[mt][2] = Ap[(rm + g    ) * GSW + kt * 8 + t + 4];
                a[mt][3] = Ap[(rm + g + 8) * GSW + kt * 8 + t + 4];
            }
            #pragma unroll
            for (int nt = 0; nt < 4; nt++) {
                int nb = wn * 32 + nt * 8;
                uint32_t b0 = Bp[(nb + g) * GSW + kt * 8 + t    ];
                uint32_t b1 = Bp[(nb + g) * GSW + kt * 8 + t + 4];
                mma_bf16(c[0][nt], a[0], b0, b1);
                mma_bf16(c[1][nt], a[1], b0, b1);
            }
        }
        __syncthreads();
        buf ^= 1;
    }

    if (do_rope) {
        // Stage output tile (bias added) as bf16 in reused As smem,
        // then apply RoPE and write q/k directly.
        uint32_t* tile = &As[0][0];   // 128 x RT_STRIDE words
        #pragma unroll
        for (int mt = 0; mt < 2; mt++) {
            #pragma unroll
            for (int nt = 0; nt < 4; nt++) {
                int lr = wm * 32 + mt * 16 + g;
                int cc = wn * 32 + nt * 8 + 2 * t;
                float b0 = bias[col0 + cc], b1 = bias[col0 + cc + 1];
                int w = wn * 16 + nt * 4 + t;
                tile[lr * RT_STRIDE + w] =
                    packbf(c[mt][nt][0] + b0, c[mt][nt][1] + b1);
                tile[(lr + 8) * RT_STRIDE + w] =
                    packbf(c[mt][nt][2] + b0, c[mt][nt][3] + b1);
            }
        }
        __syncthreads();

        __nv_bfloat16* out = (__nv_bfloat16*)outv;
        const int sbase = row0 & (SS - 1);
        #pragma unroll
        for (int i = 0; i < 4; i++) {
            int task = tid + i * 256;        // 1024 tasks: 128 rows x 8 d-groups
            int r  = task >> 3;
            int dg = task & 7;
            uint32_t wa0 = tile[r * RT_STRIDE + dg * 2    ];
            uint32_t wa1 = tile[r * RT_STRIDE + dg * 2 + 1];
            uint32_t wb0 = tile[r * RT_STRIDE + dg * 2 + 16];
            uint32_t wb1 = tile[r * RT_STRIDE + dg * 2 + 17];
            float a0 = bflo(wa0), a1 = bfhi(wa0), a2 = bflo(wa1), a3 = bfhi(wa1);
            float b0 = bflo(wb0), b1 = bfhi(wb0), b2 = bflo(wb1), b3 = bfhi(wb1);
            int s = sbase + r;
            float4 c1 = *(const float4*)&cosb[s * HDD + dg * 4];
            float4 s1 = *(const float4*)&sinb[s * HDD + dg * 4];
            float4 c2 = *(const float4*)&cosb[s * HDD + dg * 4 + 32];
            float4 s2 = *(const float4*)&sinb[s * HDD + dg * 4 + 32];
            float o0 = (a0 * c1.x - b0 * s1.x) * qscale;
            float o1 = (a1 * c1.y - b1 * s1.y) * qscale;
            float o2 = (a2 * c1.z - b2 * s1.z) * qscale;
            float o3 = (a3 * c1.w - b3 * s1.w) * qscale;
            float p0 = (b0 * c2.x + a0 * s2.x) * qscale;
            float p1 = (b1 * c2.y + a1 * s2.y) * qscale;
            float p2 = (b2 * c2.z + a2 * s2.z) * qscale;
            float p3 = (b3 * c2.w + a3 * s2.w) * qscale;
            __nv_bfloat16* op = out + (size_t)(row0 + r) * DMD + col0 + dg * 4;
            uint2 w1; w1.x = packbf(o0, o1); w1.y = packbf(o2, o3);
            uint2 w2; w2.x = packbf(p0, p1); w2.y = packbf(p2, p3);
            *(uint2*)op = w1;
            *(uint2*)(op + 32) = w2;
        }
        return;
    }

    #pragma unroll
    for (int mt = 0; mt < 2; mt++) {
        #pragma unroll
        for (int nt = 0; nt < 4; nt++) {
            int r0 = row0 + wm * 32 + mt * 16 + g;
            int cc = col0 + wn * 32 + nt * 8 + 2 * t;
            float v0 = c[mt][nt][0], v1 = c[mt][nt][1];
            float v2 = c[mt][nt][2], v3 = c[mt][nt][3];
            if (bias) {
                float b0 = bias[cc], b1 = bias[cc + 1];
                v0 += b0; v1 += b1; v2 += b0; v3 += b1;
            }
            if constexpr (HAS_RES) {
                v0 += residual[(size_t)r0 * DMD + cc];
                v1 += residual[(size_t)r0 * DMD + cc + 1];
                v2 += residual[(size_t)(r0 + 8) * DMD + cc];
                v3 += residual[(size_t)(r0 + 8) * DMD + cc + 1];
            }
            if constexpr (OUT_BF16) {
                __nv_bfloat16* out = (__nv_bfloat16*)outv;
                *(uint32_t*)&out[(size_t)r0 * DMD + cc]       = packbf(v0, v1);
                *(uint32_t*)&out[(size_t)(r0 + 8) * DMD + cc] = packbf(v2, v3);
            } else {
                float* out = (float*)outv;
                *(float2*)&out[(size_t)r0 * DMD + cc]       = make_float2(v0, v1);
                *(float2*)&out[(size_t)(r0 + 8) * DMD + cc] = make_float2(v2, v3);
            }
        }
    }
}

// Fused QKV projection + RoPE. grid.z in {0,1,2}: q (rope+scale), k (rope), v.
__global__ __launch_bounds__(256) void qkv_gemm(
    const __nv_bfloat16* __restrict__ X,
    const __nv_bfloat16* __restrict__ Wq, const __nv_bfloat16* __restrict__ Wk,
    const __nv_bfloat16* __restrict__ Wv,
    const float* __restrict__ bq, const float* __restrict__ bk,
    const float* __restrict__ bv,
    const float* __restrict__ cosb, const float* __restrict__ sinb,
    __nv_bfloat16* __restrict__ q, __nv_bfloat16* __restrict__ k,
    __nv_bfloat16* __restrict__ v)
{
    __shared__ uint32_t As[2][128*GSW];
    __shared__ uint32_t Bs[2][64*GSW];
    int z = blockIdx.z;
    const __nv_bfloat16* W = (z == 0) ? Wq : (z == 1) ? Wk : Wv;
    const float* bias      = (z == 0) ? bq : (z == 1) ? bk : bv;
    __nv_bfloat16* out     = (z == 0) ? q  : (z == 1) ? k  : v;
    // q carries log2(e)/HD (both SCALING factors + exp->exp2 conversion)
    float qscale = (z == 0) ? (1.4426950408889634f / (float)HDD) : 1.0f;
    gemm_body<true, false>(X, W, bias, nullptr, out, As, Bs,
                           cosb, sinb, qscale, z < 2);
}

__global__ __launch_bounds__(256) void oproj_gemm(
    const __nv_bfloat16* __restrict__ X, const __nv_bfloat16* __restrict__ W,
    const float* __restrict__ residual, float* __restrict__ out)
{
    __shared__ uint32_t As[2][128*GSW];
    __shared__ uint32_t Bs[2][64*GSW];
    gemm_body<false, true>(X, W, nullptr, residual, out, As, Bs,
                           nullptr, nullptr, 1.0f, false);
}

// ---------------------------------------------------------------------------
// Flash attention, bf16 MMA. CTA = 128 threads (4 warps), 128 q-rows,
// each warp owns 32 rows (2 x m16). KV tiles of 64 keys, cp.async
// THREE-stage pipeline, prefetch distance 2, ONE barrier per tile.
// Tile body SOFTWARE-PIPELINED at key-block granularity: S-MMA(j) issues,
// then exp/pack/ones-MMA/PV-MMA of key-block j-1 — MUFU exp overlaps tensor
// work instead of phase-serializing (measured tensor 59% -> target ~80%).
// ---------------------------------------------------------------------------
#define KSW 36
#define ATTN_SMEM ((128*KSW + 6*64*KSW) * 4)   // 73728 B

__global__ __launch_bounds__(128, 2) void attn_mma(
    const __nv_bfloat16* __restrict__ Q, const __nv_bfloat16* __restrict__ K,
    const __nv_bfloat16* __restrict__ V, __nv_bfloat16* __restrict__ O)
{
    extern __shared__ uint32_t dsm[];
    uint32_t* Qs = dsm;                                  // 128 x KSW
    uint32_t ksa[3], vsa[3];
    #pragma unroll
    for (int s = 0; s < 3; s++) {
        ksa[s] = smaddr(dsm + 128*KSW + s * 64*KSW);
        vsa[s] = smaddr(dsm + 128*KSW + (3 + s) * 64*KSW);
    }

    const int tid  = threadIdx.x;
    const int warp = tid >> 5;
    const int lane = tid & 31;
    const int g    = lane >> 2;
    const int t    = lane & 3;
    const int rm   = warp * 32;
    const int bh   = blockIdx.y;
    const int b    = bh / NH, h = bh % NH;
    const int s0   = blockIdx.x * 128;

    const __nv_bfloat16* Qb = Q + (size_t)b * SS * DMD + h * HDD;
    const __nv_bfloat16* Kb = K + (size_t)b * SS * DMD + h * HDD;
    const __nv_bfloat16* Vb = V + (size_t)b * SS * DMD + h * HDD;

    uint32_t qsa = smaddr(Qs);
    const int kvr  = tid >> 3;          // 0..15 base row
    const int kvc8 = (tid & 7) * 8;

    // Prologue: group0 = Q + KV tile0, group1 = KV tile1
    #pragma unroll
    for (int it = 0; it < 8; it++) {
        int i = tid + it * 128;
        int r = i >> 3, c8 = (i & 7) * 8;
        cp16(qsa + (r * KSW + c8/2) * 4, Qb + (size_t)(s0 + r) * DMD + c8);
    }
    #pragma unroll
    for (int it = 0; it < 4; it++) {
        int r = kvr + it * 16;
        cp16(ksa[0] + (r * KSW + kvc8/2) * 4, Kb + (size_t)r * DMD + kvc8);
        cp16(vsa[0] + (r * KSW + kvc8/2) * 4, Vb + (size_t)r * DMD + kvc8);
    }
    cp_commit();
    #pragma unroll
    for (int it = 0; it < 4; it++) {
        int r = kvr + it * 16;
        cp16(ksa[1] + (r * KSW + kvc8/2) * 4, Kb + (size_t)(64 + r) * DMD + kvc8);
        cp16(vsa[1] + (r * KSW + kvc8/2) * 4, Vb + (size_t)(64 + r) * DMD + kvc8);
    }
    cp_commit();

    // ldmatrix lane addressing
    const int krow_i = (lane & 7) + (lane >> 4) * 8;
    const int kcol_i = ((lane >> 3) & 1) * 4;
    const int vrow   = (lane & 7) + ((lane >> 3) & 1) * 8;
    const int vcolw  = (lane >> 4) * 4;

    const uint32_t ONES = 0x3F803F80u;   // bf16x2 {1.0, 1.0}

    float o[2][8][4] = {};
    float lsum[2][4] = {};
    uint32_t qa[2][4][4];
    bool qload = false;

    const int NT = SS / 64;   // 64 tiles
    for (int it = 0; it < NT; it++) {
        if (it < NT - 1) cp_wait<1>(); else cp_wait<0>();
        __syncthreads();

        if (!qload) {   // first iteration: Q is ready now
            qload = true;
            #pragma unroll
            for (int mt = 0; mt < 2; mt++) {
                int rb = rm + mt * 16;
                #pragma unroll
                for (int kt = 0; kt < 4; kt++) {
                    qa[mt][kt][0] = Qs[(rb + g    ) * KSW + kt * 8 + t    ];
                    qa[mt][kt][1] = Qs[(rb + g + 8) * KSW + kt * 8 + t    ];
                    qa[mt][kt][2] = Qs[(rb + g    ) * KSW + kt * 8 + t + 4];
                    qa[mt][kt][3] = Qs[(rb + g + 8) * KSW + kt * 8 + t + 4];
                }
            }
        }

        const int st = it % 3;
        float s[2][8][4] = {};

        // Process key-block j: exp, pack, l += P@ones, O += P(j) V(j)
        auto process = [&](int j) {
            #pragma unroll
            for (int m = 0; m < 2; m++) {
                #pragma unroll
                for (int q = 0; q < 4; q++) {
                    s[m][2*j  ][q] = ex2f(s[m][2*j  ][q]);
                    s[m][2*j+1][q] = ex2f(s[m][2*j+1][q]);
                }
            }
            uint32_t pa0[4], pa1[4];
            pa0[0] = packbf(s[0][2*j  ][0], s[0][2*j  ][1]);
            pa0[1] = packbf(s[0][2*j  ][2], s[0][2*j  ][3]);
            pa0[2] = packbf(s[0][2*j+1][0], s[0][2*j+1][1]);
            pa0[3] = packbf(s[0][2*j+1][2], s[0][2*j+1][3]);
            pa1[0] = packbf(s[1][2*j  ][0], s[1][2*j  ][1]);
            pa1[1] = packbf(s[1][2*j  ][2], s[1][2*j  ][3]);
            pa1[2] = packbf(s[1][2*j+1][0], s[1][2*j+1][1]);
            pa1[3] = packbf(s[1][2*j+1][2], s[1][2*j+1][3]);
            mma_bf16(lsum[0], pa0, ONES, ONES);
            mma_bf16(lsum[1], pa1, ONES, ONES);
            #pragma unroll
            for (int np = 0; np < 4; np++) {
                uint32_t b0, b1, b2, b3;
                uint32_t addr = vsa[st] +
                    (((j*16 + vrow) * KSW) + np*8 + vcolw) * 4;
                ldsm4t(b0, b1, b2, b3, addr);
                mma_bf16(o[0][2*np  ], pa0, b0, b1);
                mma_bf16(o[0][2*np+1], pa0, b2, b3);
                mma_bf16(o[1][2*np  ], pa1, b0, b1);
                mma_bf16(o[1][2*np+1], pa1, b2, b3);
            }
        };

        // Pipelined: S-MMA(ntp) issues, then process(ntp-1) overlaps with it
        #pragma unroll
        for (int ntp = 0; ntp < 4; ntp++) {
            #pragma unroll
            for (int kt = 0; kt < 4; kt++) {
                uint32_t r0, r1, r2, r3;
                uint32_t addr = ksa[st] +
                    (((ntp * 16 + krow_i) * KSW) + kt * 8 + kcol_i) * 4;
                ldsm4(r0, r1, r2, r3, addr);
                mma_bf16(s[0][2*ntp  ], qa[0][kt], r0, r1);
                mma_bf16(s[1][2*ntp  ], qa[1][kt], r0, r1);
                mma_bf16(s[0][2*ntp+1], qa[0][kt], r2, r3);
                mma_bf16(s[1][2*ntp+1], qa[1][kt], r2, r3);
            }
            if (ntp > 0) process(ntp - 1);
        }
        process(3);

        // Prefetch tile it+2 into stage (it+2)%3 (after compute; safe w/ 3 stages)
        if (it + 2 < NT) {
            const int ps = (it + 2) % 3;
            const __nv_bfloat16* Kg = Kb + (size_t)(it + 2) * 64 * DMD;
            const __nv_bfloat16* Vg = Vb + (size_t)(it + 2) * 64 * DMD;
            #pragma unroll
            for (int j = 0; j < 4; j++) {
                int r = kvr + j * 16;
                cp16(ksa[ps] + (r * KSW + kvc8/2) * 4, Kg + (size_t)r * DMD + kvc8);
                cp16(vsa[ps] + (r * KSW + kvc8/2) * 4, Vg + (size_t)r * DMD + kvc8);
            }
            cp_commit();
        }
    }

    // Normalize (lsum[mt][0] = row rm+g sum; lsum[mt][2] = row rm+g+8 sum)
    float inv[2][2];
    inv[0][0] = 1.0f / lsum[0][0];  inv[0][1] = 1.0f / lsum[0][2];
    inv[1][0] = 1.0f / lsum[1][0];  inv[1][1] = 1.0f / lsum[1][2];

    __nv_bfloat16* Ob = O + (size_t)b * SS * DMD + h * HDD;
    #pragma unroll
    for (int mt = 0; mt < 2; mt++) {
        int rb = s0 + rm + mt * 16;
        #pragma unroll
        for (int nt = 0; nt < 8; nt++) {
            int cc = nt * 8 + 2 * t;
            *(uint32_t*)&Ob[(size_t)(rb + g) * DMD + cc] =
                packbf(o[mt][nt][0] * inv[mt][0], o[mt][nt][1] * inv[mt][0]);
            *(uint32_t*)&Ob[(size_t)(rb + g + 8) * DMD + cc] =
                packbf(o[mt][nt][2] * inv[mt][1], o[mt][nt][3] * inv[mt][1]);
        }
    }
}

// ---------------------------------------------------------------------------
// LayerNorm over rows of 768. One block per row.
// ---------------------------------------------------------------------------
__global__ __launch_bounds__(256) void ln_kernel(
    const float* __restrict__ X, const float* __restrict__ gamma,
    const float* __restrict__ beta, float* __restrict__ out)
{
    const int row = blockIdx.x;
    const float* xr = X + (size_t)row * DMD;
    const int t = threadIdx.x;
    float x0 = xr[t], x1 = xr[t + 256], x2 = xr[t + 512];
    float sum = x0 + x1 + x2;
    float sq  = x0*x0 + x1*x1 + x2*x2;
    #pragma unroll
    for (int off = 16; off > 0; off >>= 1) {
        sum += __shfl_xor_sync(0xffffffffu, sum, off);
        sq  += __shfl_xor_sync(0xffffffffu, sq,  off);
    }
    __shared__ float wsum[8], wsq[8];
    __shared__ float s_mean, s_rstd;
    int wid = t >> 5, lane = t & 31;
    if (lane == 0) { wsum[wid] = sum; wsq[wid] = sq; }
    __syncthreads();
    if (t == 0) {
        float ts = 0.f, tq = 0.f;
        #pragma unroll
        for (int i = 0; i < 8; i++) { ts += wsum[i]; tq += wsq[i]; }
        float mean = ts * (1.0f / DMD);
        float var  = tq * (1.0f / DMD) - mean * mean;
        s_mean = mean;
        s_rstd = rsqrtf(var + 1e-12f);
    }
    __syncthreads();
    float mean = s_mean, rstd = s_rstd;
    out[(size_t)row*DMD + t      ] = (x0 - mean)*rstd*gamma[t      ] + beta[t      ];
    out[(size_t)row*DMD + t + 256] = (x1 - mean)*rstd*gamma[t + 256] + beta[t + 256];
    out[(size_t)row*DMD + t + 512] = (x2 - mean)*rstd*gamma[t + 512] + beta[t + 512];
}

// ---------------------------------------------------------------------------
extern "C" void kernel_launch(void* const* d_in, const int* in_sizes, int n_in,
                              void* d_out, int out_size)
{
    const float* hidden = (const float*)d_in[0];
    const float* cosb   = (const float*)d_in[1];
    const float* sinb   = (const float*)d_in[2];
    const float* Wq     = (const float*)d_in[3];
    const float* bq     = (const float*)d_in[4];
    const float* Wk     = (const float*)d_in[5];
    const float* bk     = (const float*)d_in[6];
    const float* Wv     = (const float*)d_in[7];
    const float* bv     = (const float*)d_in[8];
    const float* Wo     = (const float*)d_in[9];
    const float* ln_g   = (const float*)d_in[10];
    const float* ln_b   = (const float*)d_in[11];

    __nv_bfloat16 *qp, *kp, *vp, *ap, *xp, *wqp, *wkp, *wvp, *wop;
    float *tp;
    cudaGetSymbolAddress((void**)&qp,  g_q);
    cudaGetSymbolAddress((void**)&kp,  g_k);
    cudaGetSymbolAddress((void**)&vp,  g_v);
    cudaGetSymbolAddress((void**)&ap,  g_attn);
    cudaGetSymbolAddress((void**)&xp,  g_x);
    cudaGetSymbolAddress((void**)&wqp, g_wq);
    cudaGetSymbolAddress((void**)&wkp, g_wk);
    cudaGetSymbolAddress((void**)&wvp, g_wv);
    cudaGetSymbolAddress((void**)&wop, g_wo);
    cudaGetSymbolAddress((void**)&tp,  g_tmp);

    // Raise dynamic-smem cap for attn_mma (73.7 KB > 48 KB default).
    cudaFuncSetAttribute(attn_mma,
                         cudaFuncAttributeMaxDynamicSharedMemorySize, ATTN_SMEM);

    // Convert inputs to bf16 (hidden + all 4 weights fused)
    f2bf<<<(MROWS*DMD/4 + 255)/256, 256>>>(hidden, xp, MROWS*DMD);
    f2bf_w4<<<dim3((DMD*DMD/4 + 255)/256, 4), 256>>>(
        Wq, Wk, Wv, Wo, wqp, wkp, wvp, wop);

    // Fused QKV projections + RoPE (rope applied in epilogue for q, k)
    qkv_gemm<<<dim3(DMD/64, MROWS/128, 3), 256>>>(
        xp, wqp, wkp, wvp, bq, bk, bv, cosb, sinb, qp, kp, vp);

    attn_mma<<<dim3(SS/128, BB*NH), 128, ATTN_SMEM>>>(qp, kp, vp, ap);

    // out-proj + residual into tmp (fp32 for LN)
    oproj_gemm<<<dim3(DMD/64, MROWS/128), 256>>>(ap, wop, hidden, tp);

    ln_kernel<<<MROWS, 256>>>(tp, ln_g, ln_b, (float*)d_out);
}

// round 16
// speedup vs baseline: 1.0447x; 1.0447x over previous
#include <cuda_runtime.h>
#include <cuda_bf16.h>
#include <math.h>
#include <stdint.h>

#define BB 2
#define SS 4096
#define DMD 768
#define NH 12
#define HDD 64
#define MROWS (BB*SS)

// Scratch (static device globals — allocation-free rule)
__device__ __align__(16) __nv_bfloat16 g_q[MROWS*DMD];
__device__ __align__(16) __nv_bfloat16 g_k[MROWS*DMD];
__device__ __align__(16) __nv_bfloat16 g_v[MROWS*DMD];
__device__ __align__(16) __nv_bfloat16 g_attn[MROWS*DMD];
__device__ __align__(16) __nv_bfloat16 g_x[MROWS*DMD];
__device__ __align__(16) __nv_bfloat16 g_wq[DMD*DMD];
__device__ __align__(16) __nv_bfloat16 g_wk[DMD*DMD];
__device__ __align__(16) __nv_bfloat16 g_wv[DMD*DMD];
__device__ __align__(16) __nv_bfloat16 g_wo[DMD*DMD];
__device__ __align__(16) float         g_tmp[MROWS*DMD];

// ---------------------------------------------------------------------------
// Helpers
// ---------------------------------------------------------------------------
__device__ __forceinline__ uint32_t packbf(float a, float b) {
    __nv_bfloat162 h = __floats2bfloat162_rn(a, b);
    return *(uint32_t*)&h;
}
__device__ __forceinline__ float bflo(uint32_t w) {
    return __bfloat162float(*(__nv_bfloat16*)&w);
}
__device__ __forceinline__ float bfhi(uint32_t w) {
    uint16_t h = (uint16_t)(w >> 16);
    return __bfloat162float(*(__nv_bfloat16*)&h);
}
__device__ __forceinline__ float ex2f(float x) {
    float y;
    asm("ex2.approx.f32 %0, %1;" : "=f"(y) : "f"(x));
    return y;
}
__device__ __forceinline__ void mma_bf16(float* c, const uint32_t* a,
                                         uint32_t b0, uint32_t b1) {
    asm volatile(
        "mma.sync.aligned.m16n8k16.row.col.f32.bf16.bf16.f32 "
        "{%0,%1,%2,%3}, {%4,%5,%6,%7}, {%8,%9}, {%0,%1,%2,%3};"
        : "+f"(c[0]), "+f"(c[1]), "+f"(c[2]), "+f"(c[3])
        : "r"(a[0]), "r"(a[1]), "r"(a[2]), "r"(a[3]), "r"(b0), "r"(b1));
}
__device__ __forceinline__ void cp16(uint32_t s, const void* g) {
    asm volatile("cp.async.cg.shared.global [%0], [%1], 16;" :: "r"(s), "l"(g));
}
__device__ __forceinline__ void cp_commit() {
    asm volatile("cp.async.commit_group;");
}
template<int N> __device__ __forceinline__ void cp_wait() {
    asm volatile("cp.async.wait_group %0;" :: "n"(N));
}
__device__ __forceinline__ void ldsm4(uint32_t& r0, uint32_t& r1,
                                      uint32_t& r2, uint32_t& r3, uint32_t a) {
    asm volatile("ldmatrix.sync.aligned.m8n8.x4.shared.b16 "
                 "{%0,%1,%2,%3}, [%4];"
                 : "=r"(r0), "=r"(r1), "=r"(r2), "=r"(r3) : "r"(a));
}
__device__ __forceinline__ void ldsm4t(uint32_t& r0, uint32_t& r1,
                                       uint32_t& r2, uint32_t& r3, uint32_t a) {
    asm volatile("ldmatrix.sync.aligned.m8n8.x4.trans.shared.b16 "
                 "{%0,%1,%2,%3}, [%4];"
                 : "=r"(r0), "=r"(r1), "=r"(r2), "=r"(r3) : "r"(a));
}
__device__ __forceinline__ uint32_t smaddr(const void* p) {
    return (uint32_t)__cvta_generic_to_shared(p);
}

// ---------------------------------------------------------------------------
// fp32 -> bf16 conversion (vectorized); single-tensor and fused 4-weight forms
// ---------------------------------------------------------------------------
__global__ __launch_bounds__(256) void f2bf(
    const float* __restrict__ in, __nv_bfloat16* __restrict__ out, int n)
{
    int i = (blockIdx.x * blockDim.x + threadIdx.x) * 4;
    if (i >= n) return;
    float4 v = *(const float4*)(in + i);
    uint2 o;
    o.x = packbf(v.x, v.y);
    o.y = packbf(v.z, v.w);
    *(uint2*)(out + i) = o;
}

__global__ __launch_bounds__(256) void f2bf_w4(
    const float* __restrict__ w0, const float* __restrict__ w1,
    const float* __restrict__ w2, const float* __restrict__ w3,
    __nv_bfloat16* __restrict__ o0, __nv_bfloat16* __restrict__ o1,
    __nv_bfloat16* __restrict__ o2, __nv_bfloat16* __restrict__ o3)
{
    int z = blockIdx.y;
    const float* in = (z == 0) ? w0 : (z == 1) ? w1 : (z == 2) ? w2 : w3;
    __nv_bfloat16* out = (z == 0) ? o0 : (z == 1) ? o1 : (z == 2) ? o2 : o3;
    int i = (blockIdx.x * blockDim.x + threadIdx.x) * 4;
    if (i >= DMD * DMD) return;
    float4 v = *(const float4*)(in + i);
    uint2 o;
    o.x = packbf(v.x, v.y);
    o.y = packbf(v.z, v.w);
    *(uint2*)(out + i) = o;
}

// ---------------------------------------------------------------------------
// bf16 GEMM core: out[M,N] = X[M,K] @ W[N,K]^T (+bias) (+residual)
// Tile 128x64, BK=32, 8 warps (4m x 2n), cp.async double-buffered.
// Optional fused RoPE epilogue (for Q/K projections).
// ---------------------------------------------------------------------------
#define GSW 20
#define RT_STRIDE 34   // rope tile row stride in words (68 bf16)

template<bool OUT_BF16, bool HAS_RES>
__device__ __forceinline__ void gemm_body(
    const __nv_bfloat16* __restrict__ X, const __nv_bfloat16* __restrict__ W,
    const float* __restrict__ bias, const float* __restrict__ residual,
    void* __restrict__ outv,
    uint32_t (*As)[128*GSW], uint32_t (*Bs)[64*GSW],
    const float* __restrict__ cosb, const float* __restrict__ sinb,
    float qscale, bool do_rope)
{
    const int tid  = threadIdx.x;
    const int warp = tid >> 5;
    const int lane = tid & 31;
    const int g    = lane >> 2;
    const int t    = lane & 3;
    const int wm   = warp & 3;
    const int wn   = warp >> 2;
    const int row0 = blockIdx.y * 128;
    const int col0 = blockIdx.x * 64;

    uint32_t asa[2] = { smaddr(As[0]), smaddr(As[1]) };
    uint32_t bsa[2] = { smaddr(Bs[0]), smaddr(Bs[1]) };

    const int ar = tid >> 2;
    const int ac8 = (tid & 3) * 8;

    {
        cp16(asa[0] + (ar * GSW + ac8/2) * 4, X + (size_t)(row0 + ar) * DMD + ac8);
        cp16(asa[0] + ((ar + 64) * GSW + ac8/2) * 4,
             X + (size_t)(row0 + ar + 64) * DMD + ac8);
        cp16(bsa[0] + (ar * GSW + ac8/2) * 4, W + (size_t)(col0 + ar) * DMD + ac8);
        cp_commit();
    }

    float c[2][4][4] = {};
    int buf = 0;

    const int NKI = DMD / 32;
    for (int ki = 0; ki < NKI; ki++) {
        if (ki + 1 < NKI) {
            const int k0 = (ki + 1) * 32;
            const int nb = buf ^ 1;
            cp16(asa[nb] + (ar * GSW + ac8/2) * 4,
                 X + (size_t)(row0 + ar) * DMD + k0 + ac8);
            cp16(asa[nb] + ((ar + 64) * GSW + ac8/2) * 4,
                 X + (size_t)(row0 + ar + 64) * DMD + k0 + ac8);
            cp16(bsa[nb] + (ar * GSW + ac8/2) * 4,
                 W + (size_t)(col0 + ar) * DMD + k0 + ac8);
            cp_commit();
            cp_wait<1>();
        } else {
            cp_wait<0>();
        }
        __syncthreads();

        const uint32_t* Ap = As[buf];
        const uint32_t* Bp = Bs[buf];
        #pragma unroll
        for (int kt = 0; kt < 2; kt++) {
            uint32_t a[2][4];
            #pragma unroll
            for (int mt = 0; mt < 2; mt++) {
                int rm = wm * 32 + mt * 16;
                a[mt][0] = Ap[(rm + g    ) * GSW + kt * 8 + t    ];
                a[mt][1] = Ap[(rm + g + 8) * GSW + kt * 8 + t    ];
                a[mt][2] = Ap[(rm + g    ) * GSW + kt * 8 + t + 4];
                a[mt][3] = Ap[(rm + g + 8) * GSW + kt * 8 + t + 4];
            }
            #pragma unroll
            for (int nt = 0; nt < 4; nt++) {
                int nb = wn * 32 + nt * 8;
                uint32_t b0 = Bp[(nb + g) * GSW + kt * 8 + t    ];
                uint32_t b1 = Bp[(nb + g) * GSW + kt * 8 + t + 4];
                mma_bf16(c[0][nt], a[0], b0, b1);
                mma_bf16(c[1][nt], a[1], b0, b1);
            }
        }
        __syncthreads();
        buf ^= 1;
    }

    if (do_rope) {
        uint32_t* tile = &As[0][0];   // 128 x RT_STRIDE words
        #pragma unroll
        for (int mt = 0; mt < 2; mt++) {
            #pragma unroll
            for (int nt = 0; nt < 4; nt++) {
                int lr = wm * 32 + mt * 16 + g;
                int cc = wn * 32 + nt * 8 + 2 * t;
                float b0 = bias[col0 + cc], b1 = bias[col0 + cc + 1];
                int w = wn * 16 + nt * 4 + t;
                tile[lr * RT_STRIDE + w] =
                    packbf(c[mt][nt][0] + b0, c[mt][nt][1] + b1);
                tile[(lr + 8) * RT_STRIDE + w] =
                    packbf(c[mt][nt][2] + b0, c[mt][nt][3] + b1);
            }
        }
        __syncthreads();

        __nv_bfloat16* out = (__nv_bfloat16*)outv;
        const int sbase = row0 & (SS - 1);
        #pragma unroll
        for (int i = 0; i < 4; i++) {
            int task = tid + i * 256;        // 1024 tasks: 128 rows x 8 d-groups
            int r  = task >> 3;
            int dg = task & 7;
            uint32_t wa0 = tile[r * RT_STRIDE + dg * 2    ];
            uint32_t wa1 = tile[r * RT_STRIDE + dg * 2 + 1];
            uint32_t wb0 = tile[r * RT_STRIDE + dg * 2 + 16];
            uint32_t wb1 = tile[r * RT_STRIDE + dg * 2 + 17];
            float a0 = bflo(wa0), a1 = bfhi(wa0), a2 = bflo(wa1), a3 = bfhi(wa1);
            float b0 = bflo(wb0), b1 = bfhi(wb0), b2 = bflo(wb1), b3 = bfhi(wb1);
            int s = sbase + r;
            float4 c1 = *(const float4*)&cosb[s * HDD + dg * 4];
            float4 s1 = *(const float4*)&sinb[s * HDD + dg * 4];
            float4 c2 = *(const float4*)&cosb[s * HDD + dg * 4 + 32];
            float4 s2 = *(const float4*)&sinb[s * HDD + dg * 4 + 32];
            float o0 = (a0 * c1.x - b0 * s1.x) * qscale;
            float o1 = (a1 * c1.y - b1 * s1.y) * qscale;
            float o2 = (a2 * c1.z - b2 * s1.z) * qscale;
            float o3 = (a3 * c1.w - b3 * s1.w) * qscale;
            float p0 = (b0 * c2.x + a0 * s2.x) * qscale;
            float p1 = (b1 * c2.y + a1 * s2.y) * qscale;
            float p2 = (b2 * c2.z + a2 * s2.z) * qscale;
            float p3 = (b3 * c2.w + a3 * s2.w) * qscale;
            __nv_bfloat16* op = out + (size_t)(row0 + r) * DMD + col0 + dg * 4;
            uint2 w1; w1.x = packbf(o0, o1); w1.y = packbf(o2, o3);
            uint2 w2; w2.x = packbf(p0, p1); w2.y = packbf(p2, p3);
            *(uint2*)op = w1;
            *(uint2*)(op + 32) = w2;
        }
        return;
    }

    #pragma unroll
    for (int mt = 0; mt < 2; mt++) {
        #pragma unroll
        for (int nt = 0; nt < 4; nt++) {
            int r0 = row0 + wm * 32 + mt * 16 + g;
            int cc = col0 + wn * 32 + nt * 8 + 2 * t;
            float v0 = c[mt][nt][0], v1 = c[mt][nt][1];
            float v2 = c[mt][nt][2], v3 = c[mt][nt][3];
            if (bias) {
                float b0 = bias[cc], b1 = bias[cc + 1];
                v0 += b0; v1 += b1; v2 += b0; v3 += b1;
            }
            if constexpr (HAS_RES) {
                v0 += residual[(size_t)r0 * DMD + cc];
                v1 += residual[(size_t)r0 * DMD + cc + 1];
                v2 += residual[(size_t)(r0 + 8) * DMD + cc];
                v3 += residual[(size_t)(r0 + 8) * DMD + cc + 1];
            }
            if constexpr (OUT_BF16) {
                __nv_bfloat16* out = (__nv_bfloat16*)outv;
                *(uint32_t*)&out[(size_t)r0 * DMD + cc]       = packbf(v0, v1);
                *(uint32_t*)&out[(size_t)(r0 + 8) * DMD + cc] = packbf(v2, v3);
            } else {
                float* out = (float*)outv;
                *(float2*)&out[(size_t)r0 * DMD + cc]       = make_float2(v0, v1);
                *(float2*)&out[(size_t)(r0 + 8) * DMD + cc] = make_float2(v2, v3);
            }
        }
    }
}

// Fused QKV projection + RoPE. grid.z in {0,1,2}: q (rope+scale), k (rope), v.
__global__ __launch_bounds__(256) void qkv_gemm(
    const __nv_bfloat16* __restrict__ X,
    const __nv_bfloat16* __restrict__ Wq, const __nv_bfloat16* __restrict__ Wk,
    const __nv_bfloat16* __restrict__ Wv,
    const float* __restrict__ bq, const float* __restrict__ bk,
    const float* __restrict__ bv,
    const float* __restrict__ cosb, const float* __restrict__ sinb,
    __nv_bfloat16* __restrict__ q, __nv_bfloat16* __restrict__ k,
    __nv_bfloat16* __restrict__ v)
{
    __shared__ uint32_t As[2][128*GSW];
    __shared__ uint32_t Bs[2][64*GSW];
    int z = blockIdx.z;
    const __nv_bfloat16* W = (z == 0) ? Wq : (z == 1) ? Wk : Wv;
    const float* bias      = (z == 0) ? bq : (z == 1) ? bk : bv;
    __nv_bfloat16* out     = (z == 0) ? q  : (z == 1) ? k  : v;
    // q carries log2(e)/HD (both SCALING factors + exp->exp2 conversion)
    float qscale = (z == 0) ? (1.4426950408889634f / (float)HDD) : 1.0f;
    gemm_body<true, false>(X, W, bias, nullptr, out, As, Bs,
                           cosb, sinb, qscale, z < 2);
}

__global__ __launch_bounds__(256) void oproj_gemm(
    const __nv_bfloat16* __restrict__ X, const __nv_bfloat16* __restrict__ W,
    const float* __restrict__ residual, float* __restrict__ out)
{
    __shared__ uint32_t As[2][128*GSW];
    __shared__ uint32_t Bs[2][64*GSW];
    gemm_body<false, true>(X, W, nullptr, residual, out, As, Bs,
                           nullptr, nullptr, 1.0f, false);
}

// ---------------------------------------------------------------------------
// Flash attention, bf16 MMA. CTA = 128 threads (4 warps), 128 q-rows,
// each warp owns 32 rows (2 x m16). KV tiles of 64 keys, cp.async
// THREE-stage pipeline, prefetch distance 2, ONE barrier per tile.
// Per-key-block processing with a SMALL local S accumulator (16 regs instead
// of 64): regs drop ~216 -> ~170, enabling 3 CTAs/SM (12 warps, 3/SMSP).
// R15 showed the kernel is latency-bound at 2 warps/SMSP (issue 34%,
// tensor 59%); occupancy is the lever, not instruction scheduling.
// ---------------------------------------------------------------------------
#define KSW 36
#define ATTN_SMEM ((128*KSW + 6*64*KSW) * 4)   // 73728 B; 3 CTAs = 221 KB < 228

__global__ __launch_bounds__(128, 3) void attn_mma(
    const __nv_bfloat16* __restrict__ Q, const __nv_bfloat16* __restrict__ K,
    const __nv_bfloat16* __restrict__ V, __nv_bfloat16* __restrict__ O)
{
    extern __shared__ uint32_t dsm[];
    uint32_t* Qs = dsm;                                  // 128 x KSW
    uint32_t ksa[3], vsa[3];
    #pragma unroll
    for (int s = 0; s < 3; s++) {
        ksa[s] = smaddr(dsm + 128*KSW + s * 64*KSW);
        vsa[s] = smaddr(dsm + 128*KSW + (3 + s) * 64*KSW);
    }

    const int tid  = threadIdx.x;
    const int warp = tid >> 5;
    const int lane = tid & 31;
    const int g    = lane >> 2;
    const int t    = lane & 3;
    const int rm   = warp * 32;
    const int bh   = blockIdx.y;
    const int b    = bh / NH, h = bh % NH;
    const int s0   = blockIdx.x * 128;

    const __nv_bfloat16* Qb = Q + (size_t)b * SS * DMD + h * HDD;
    const __nv_bfloat16* Kb = K + (size_t)b * SS * DMD + h * HDD;
    const __nv_bfloat16* Vb = V + (size_t)b * SS * DMD + h * HDD;

    uint32_t qsa = smaddr(Qs);
    const int kvr  = tid >> 3;          // 0..15 base row
    const int kvc8 = (tid & 7) * 8;

    // Prologue: group0 = Q + KV tile0, group1 = KV tile1
    #pragma unroll
    for (int it = 0; it < 8; it++) {
        int i = tid + it * 128;
        int r = i >> 3, c8 = (i & 7) * 8;
        cp16(qsa + (r * KSW + c8/2) * 4, Qb + (size_t)(s0 + r) * DMD + c8);
    }
    #pragma unroll
    for (int it = 0; it < 4; it++) {
        int r = kvr + it * 16;
        cp16(ksa[0] + (r * KSW + kvc8/2) * 4, Kb + (size_t)r * DMD + kvc8);
        cp16(vsa[0] + (r * KSW + kvc8/2) * 4, Vb + (size_t)r * DMD + kvc8);
    }
    cp_commit();
    #pragma unroll
    for (int it = 0; it < 4; it++) {
        int r = kvr + it * 16;
        cp16(ksa[1] + (r * KSW + kvc8/2) * 4, Kb + (size_t)(64 + r) * DMD + kvc8);
        cp16(vsa[1] + (r * KSW + kvc8/2) * 4, Vb + (size_t)(64 + r) * DMD + kvc8);
    }
    cp_commit();

    // ldmatrix lane addressing
    const int krow_i = (lane & 7) + (lane >> 4) * 8;
    const int kcol_i = ((lane >> 3) & 1) * 4;
    const int vrow   = (lane & 7) + ((lane >> 3) & 1) * 8;
    const int vcolw  = (lane >> 4) * 4;

    const uint32_t ONES = 0x3F803F80u;   // bf16x2 {1.0, 1.0}

    float o[2][8][4] = {};
    float lsum[2][4] = {};
    uint32_t qa[2][4][4];
    bool qload = false;

    const int NT = SS / 64;   // 64 tiles
    for (int it = 0; it < NT; it++) {
        if (it < NT - 1) cp_wait<1>(); else cp_wait<0>();
        __syncthreads();

        if (!qload) {   // first iteration: Q is ready now
            qload = true;
            #pragma unroll
            for (int mt = 0; mt < 2; mt++) {
                int rb = rm + mt * 16;
                #pragma unroll
                for (int kt = 0; kt < 4; kt++) {
                    qa[mt][kt][0] = Qs[(rb + g    ) * KSW + kt * 8 + t    ];
                    qa[mt][kt][1] = Qs[(rb + g + 8) * KSW + kt * 8 + t    ];
                    qa[mt][kt][2] = Qs[(rb + g    ) * KSW + kt * 8 + t + 4];
                    qa[mt][kt][3] = Qs[(rb + g + 8) * KSW + kt * 8 + t + 4];
                }
            }
        }

        const int st = it % 3;

        // Per key-block (16 keys): S into small local acc, then exp/PV.
        #pragma unroll
        for (int ntp = 0; ntp < 4; ntp++) {
            float sl[2][2][4] = {};   // [m-tile][n8-pair][frag]
            #pragma unroll
            for (int kt = 0; kt < 4; kt++) {
                uint32_t r0, r1, r2, r3;
                uint32_t addr = ksa[st] +
                    (((ntp * 16 + krow_i) * KSW) + kt * 8 + kcol_i) * 4;
                ldsm4(r0, r1, r2, r3, addr);
                mma_bf16(sl[0][0], qa[0][kt], r0, r1);
                mma_bf16(sl[1][0], qa[1][kt], r0, r1);
                mma_bf16(sl[0][1], qa[0][kt], r2, r3);
                mma_bf16(sl[1][1], qa[1][kt], r2, r3);
            }

            // p = exp2(s)
            #pragma unroll
            for (int m = 0; m < 2; m++)
                #pragma unroll
                for (int p = 0; p < 2; p++)
                    #pragma unroll
                    for (int q = 0; q < 4; q++)
                        sl[m][p][q] = ex2f(sl[m][p][q]);

            uint32_t pa0[4], pa1[4];
            pa0[0] = packbf(sl[0][0][0], sl[0][0][1]);
            pa0[1] = packbf(sl[0][0][2], sl[0][0][3]);
            pa0[2] = packbf(sl[0][1][0], sl[0][1][1]);
            pa0[3] = packbf(sl[0][1][2], sl[0][1][3]);
            pa1[0] = packbf(sl[1][0][0], sl[1][0][1]);
            pa1[1] = packbf(sl[1][0][2], sl[1][0][3]);
            pa1[2] = packbf(sl[1][1][0], sl[1][1][1]);
            pa1[3] = packbf(sl[1][1][2], sl[1][1][3]);
            mma_bf16(lsum[0], pa0, ONES, ONES);
            mma_bf16(lsum[1], pa1, ONES, ONES);
            #pragma unroll
            for (int np = 0; np < 4; np++) {
                uint32_t b0, b1, b2, b3;
                uint32_t addr = vsa[st] +
                    (((ntp*16 + vrow) * KSW) + np*8 + vcolw) * 4;
                ldsm4t(b0, b1, b2, b3, addr);
                mma_bf16(o[0][2*np  ], pa0, b0, b1);
                mma_bf16(o[0][2*np+1], pa0, b2, b3);
                mma_bf16(o[1][2*np  ], pa1, b0, b1);
                mma_bf16(o[1][2*np+1], pa1, b2, b3);
            }
        }

        // Prefetch tile it+2 into stage (it+2)%3 (after compute; safe w/ 3 stages)
        if (it + 2 < NT) {
            const int ps = (it + 2) % 3;
            const __nv_bfloat16* Kg = Kb + (size_t)(it + 2) * 64 * DMD;
            const __nv_bfloat16* Vg = Vb + (size_t)(it + 2) * 64 * DMD;
            #pragma unroll
            for (int j = 0; j < 4; j++) {
                int r = kvr + j * 16;
                cp16(ksa[ps] + (r * KSW + kvc8/2) * 4, Kg + (size_t)r * DMD + kvc8);
                cp16(vsa[ps] + (r * KSW + kvc8/2) * 4, Vg + (size_t)r * DMD + kvc8);
            }
            cp_commit();
        }
    }

    // Normalize (lsum[mt][0] = row rm+g sum; lsum[mt][2] = row rm+g+8 sum)
    float inv[2][2];
    inv[0][0] = 1.0f / lsum[0][0];  inv[0][1] = 1.0f / lsum[0][2];
    inv[1][0] = 1.0f / lsum[1][0];  inv[1][1] = 1.0f / lsum[1][2];

    __nv_bfloat16* Ob = O + (size_t)b * SS * DMD + h * HDD;
    #pragma unroll
    for (int mt = 0; mt < 2; mt++) {
        int rb = s0 + rm + mt * 16;
        #pragma unroll
        for (int nt = 0; nt < 8; nt++) {
            int cc = nt * 8 + 2 * t;
            *(uint32_t*)&Ob[(size_t)(rb + g) * DMD + cc] =
                packbf(o[mt][nt][0] * inv[mt][0], o[mt][nt][1] * inv[mt][0]);
            *(uint32_t*)&Ob[(size_t)(rb + g + 8) * DMD + cc] =
                packbf(o[mt][nt][2] * inv[mt][1], o[mt][nt][3] * inv[mt][1]);
        }
    }
}

// ---------------------------------------------------------------------------
// LayerNorm over rows of 768. One block per row.
// ---------------------------------------------------------------------------
__global__ __launch_bounds__(256) void ln_kernel(
    const float* __restrict__ X, const float* __restrict__ gamma,
    const float* __restrict__ beta, float* __restrict__ out)
{
    const int row = blockIdx.x;
    const float* xr = X + (size_t)row * DMD;
    const int t = threadIdx.x;
    float x0 = xr[t], x1 = xr[t + 256], x2 = xr[t + 512];
    float sum = x0 + x1 + x2;
    float sq  = x0*x0 + x1*x1 + x2*x2;
    #pragma unroll
    for (int off = 16; off > 0; off >>= 1) {
        sum += __shfl_xor_sync(0xffffffffu, sum, off);
        sq  += __shfl_xor_sync(0xffffffffu, sq,  off);
    }
    __shared__ float wsum[8], wsq[8];
    __shared__ float s_mean, s_rstd;
    int wid = t >> 5, lane = t & 31;
    if (lane == 0) { wsum[wid] = sum; wsq[wid] = sq; }
    __syncthreads();
    if (t == 0) {
        float ts = 0.f, tq = 0.f;
        #pragma unroll
        for (int i = 0; i < 8; i++) { ts += wsum[i]; tq += wsq[i]; }
        float mean = ts * (1.0f / DMD);
        float var  = tq * (1.0f / DMD) - mean * mean;
        s_mean = mean;
        s_rstd = rsqrtf(var + 1e-12f);
    }
    __syncthreads();
    float mean = s_mean, rstd = s_rstd;
    out[(size_t)row*DMD + t      ] = (x0 - mean)*rstd*gamma[t      ] + beta[t      ];
    out[(size_t)row*DMD + t + 256] = (x1 - mean)*rstd*gamma[t + 256] + beta[t + 256];
    out[(size_t)row*DMD + t + 512] = (x2 - mean)*rstd*gamma[t + 512] + beta[t + 512];
}

// ---------------------------------------------------------------------------
extern "C" void kernel_launch(void* const* d_in, const int* in_sizes, int n_in,
                              void* d_out, int out_size)
{
    const float* hidden = (const float*)d_in[0];
    const float* cosb   = (const float*)d_in[1];
    const float* sinb   = (const float*)d_in[2];
    const float* Wq     = (const float*)d_in[3];
    const float* bq     = (const float*)d_in[4];
    const float* Wk     = (const float*)d_in[5];
    const float* bk     = (const float*)d_in[6];
    const float* Wv     = (const float*)d_in[7];
    const float* bv     = (const float*)d_in[8];
    const float* Wo     = (const float*)d_in[9];
    const float* ln_g   = (const float*)d_in[10];
    const float* ln_b   = (const float*)d_in[11];

    __nv_bfloat16 *qp, *kp, *vp, *ap, *xp, *wqp, *wkp, *wvp, *wop;
    float *tp;
    cudaGetSymbolAddress((void**)&qp,  g_q);
    cudaGetSymbolAddress((void**)&kp,  g_k);
    cudaGetSymbolAddress((void**)&vp,  g_v);
    cudaGetSymbolAddress((void**)&ap,  g_attn);
    cudaGetSymbolAddress((void**)&xp,  g_x);
    cudaGetSymbolAddress((void**)&wqp, g_wq);
    cudaGetSymbolAddress((void**)&wkp, g_wk);
    cudaGetSymbolAddress((void**)&wvp, g_wv);
    cudaGetSymbolAddress((void**)&wop, g_wo);
    cudaGetSymbolAddress((void**)&tp,  g_tmp);

    // Raise dynamic-smem cap for attn_mma (73.7 KB > 48 KB default).
    cudaFuncSetAttribute(attn_mma,
                         cudaFuncAttributeMaxDynamicSharedMemorySize, ATTN_SMEM);

    // Convert inputs to bf16 (hidden + all 4 weights fused)
    f2bf<<<(MROWS*DMD/4 + 255)/256, 256>>>(hidden, xp, MROWS*DMD);
    f2bf_w4<<<dim3((DMD*DMD/4 + 255)/256, 4), 256>>>(
        Wq, Wk, Wv, Wo, wqp, wkp, wvp, wop);

    // Fused QKV projections + RoPE (rope applied in epilogue for q, k)
    qkv_gemm<<<dim3(DMD/64, MROWS/128, 3), 256>>>(
        xp, wqp, wkp, wvp, bq, bk, bv, cosb, sinb, qp, kp, vp);

    attn_mma<<<dim3(SS/128, BB*NH), 128, ATTN_SMEM>>>(qp, kp, vp, ap);

    // out-proj + residual into tmp (fp32 for LN)
    oproj_gemm<<<dim3(DMD/64, MROWS/128), 256>>>(ap, wop, hidden, tp);

    ln_kernel<<<MROWS, 256>>>(tp, ln_g, ln_b, (float*)d_out);
}